// round 2
// baseline (speedup 1.0000x reference)
#include <cuda_runtime.h>

#define BB   8
#define CC   128
#define NN   2000
#define KK   16
#define NKS  32000          // N*K spatial per (b,c)
#define TILES 250           // NKS / 128
#define TS   128            // spatial tile
#define PADW 132            // padded row stride (floats)

// Scratch (device globals: allocation-free rule)
__device__ __align__(16) float g_h[(size_t)BB * CC * NKS];   // conv0 output, 131MB
__device__ float g_psum[BB * TILES * CC];
__device__ float g_psq [BB * TILES * CC];
__device__ float g_scale[BB * CC];
__device__ float g_shift[BB * CC];

// Load a 128x128 weight matrix (row-major [o][c]) into smem as Wsm[o][c] with
// row stride PADW. 512 threads, fully coalesced float4 loads/stores.
__device__ __forceinline__ void load_w_smem(float* Wsm, const float* __restrict__ w, int t) {
#pragma unroll
    for (int i = 0; i < 8; i++) {
        int f  = i * 512 + t;          // float4 index, 0..4095
        int o  = f >> 5;
        int c0 = (f & 31) << 2;
        float4 v = reinterpret_cast<const float4*>(w)[f];
        *reinterpret_cast<float4*>(Wsm + o * PADW + c0) = v;
    }
}

__device__ __forceinline__ float red8(float v) {
    v += __shfl_xor_sync(0xffffffffu, v, 1);
    v += __shfl_xor_sync(0xffffffffu, v, 2);
    v += __shfl_xor_sync(0xffffffffu, v, 4);
    return v;
}

// ---------------------------------------------------------------------------
// Kernel 1: h = W0 @ x_local + b0   (+ per-tile partial sum / sumsq of h)
// grid (TILES, BB), 512 threads. Each thread: 2 out-channels x 16 spatial.
// ---------------------------------------------------------------------------
__global__ __launch_bounds__(512) void k_conv0(const float* __restrict__ x,
                                               const float* __restrict__ w0,
                                               const float* __restrict__ b0) {
    extern __shared__ float sm[];
    float* Ws = sm;                 // [128][PADW]  W0 as [o][c]
    float* Xs = sm + CC * PADW;     // [128][PADW]  x tile as [c][s]

    int b = blockIdx.y, tile = blockIdx.x, t = threadIdx.x;
    int s0 = tile * TS;

    load_w_smem(Ws, w0, t);
    {
        int c = t >> 2, q = t & 3;
        const float4* src = reinterpret_cast<const float4*>(
            x + (size_t)(b * CC + c) * NKS + s0 + q * 32);
        float4* dst = reinterpret_cast<float4*>(Xs + c * PADW + q * 32);
#pragma unroll
        for (int i = 0; i < 8; i++) dst[i] = src[i];
    }
    __syncthreads();

    int o0 = (t >> 3) * 2;
    int sb = (t & 7) * 16;

    float acc[2][16];
#pragma unroll
    for (int j = 0; j < 16; j++) { acc[0][j] = 0.f; acc[1][j] = 0.f; }

#pragma unroll 4
    for (int c = 0; c < 128; c++) {
        float wr0 = Ws[o0 * PADW + c];
        float wr1 = Ws[o0 * PADW + PADW + c];
        float xr[16];
        const float4* hv = reinterpret_cast<const float4*>(Xs + c * PADW + sb);
        *reinterpret_cast<float4*>(&xr[0])  = hv[0];
        *reinterpret_cast<float4*>(&xr[4])  = hv[1];
        *reinterpret_cast<float4*>(&xr[8])  = hv[2];
        *reinterpret_cast<float4*>(&xr[12]) = hv[3];
#pragma unroll
        for (int j = 0; j < 16; j++) {
            acc[0][j] = fmaf(wr0, xr[j], acc[0][j]);
            acc[1][j] = fmaf(wr1, xr[j], acc[1][j]);
        }
    }

    float bias[2] = { b0[o0], b0[o0 + 1] };
#pragma unroll
    for (int o = 0; o < 2; o++) {
        float s = 0.f, sq = 0.f;
        float vr[16];
#pragma unroll
        for (int j = 0; j < 16; j++) {
            float v = acc[o][j] + bias[o];
            vr[j] = v; s += v; sq += v * v;
        }
        float4* dst = reinterpret_cast<float4*>(
            g_h + (size_t)(b * CC + o0 + o) * NKS + s0 + sb);
        dst[0] = *reinterpret_cast<float4*>(&vr[0]);
        dst[1] = *reinterpret_cast<float4*>(&vr[4]);
        dst[2] = *reinterpret_cast<float4*>(&vr[8]);
        dst[3] = *reinterpret_cast<float4*>(&vr[12]);
        s  = red8(s);
        sq = red8(sq);
        if ((t & 7) == 0) {
            int idx = (b * TILES + tile) * CC + o0 + o;
            g_psum[idx] = s;
            g_psq[idx]  = sq;
        }
    }
}

// ---------------------------------------------------------------------------
// Kernel 2: collapse InstanceNorm + BatchNorm into per-(b,c) affine.
// After IN, per-(b,c) mean == 0 and var == v/(v+eps_in), so BN batch mean == 0
// and BN var == mean_b[v/(v+eps_in)].  1 block, 1024 threads (t = b*128+c).
// ---------------------------------------------------------------------------
__global__ void k_stats(const float* __restrict__ bn_g, const float* __restrict__ bn_b) {
    __shared__ float rmat[BB][CC];
    __shared__ float bsc[CC];
    int t = threadIdx.x;
    int b = t >> 7, c = t & 127;

    float s = 0.f, q = 0.f;
    for (int i = 0; i < TILES; i++) {
        int idx = (b * TILES + i) * CC + c;
        s += g_psum[idx];
        q += g_psq[idx];
    }
    const float inv_n = 1.0f / (float)NKS;
    float mu  = s * inv_n;
    float var = fmaxf(q * inv_n - mu * mu, 0.f);
    rmat[b][c] = var / (var + 1e-3f);
    __syncthreads();
    if (t < CC) {
        float ss = 0.f;
#pragma unroll
        for (int i = 0; i < BB; i++) ss += rmat[i][t];
        bsc[t] = rsqrtf(ss * (1.0f / BB) + 1e-5f);
    }
    __syncthreads();
    float scale = rsqrtf(var + 1e-3f) * bsc[c] * bn_g[c];
    g_scale[b * CC + c] = scale;
    g_shift[b * CC + c] = bn_b[c] - mu * scale;
}

// ---------------------------------------------------------------------------
// Kernel 3: hn = relu(scale*h + shift); fused q,k GEMM; register softmax over
// K=16; folded v contraction; residual add.
// grid (TILES, BB), 512 threads. Thread owns 2 out-channels x 1 n (16 k's).
// ---------------------------------------------------------------------------
__global__ __launch_bounds__(512) void k_attn(
    const float* __restrict__ x_row,
    const float* __restrict__ wq, const float* __restrict__ bq,
    const float* __restrict__ wk, const float* __restrict__ bk,
    const float* __restrict__ wv, const float* __restrict__ bv,
    const float* __restrict__ gamma1, float* __restrict__ out) {
    extern __shared__ float sm[];
    float* WQ = sm;                    // [128][PADW]
    float* WK = sm + CC * PADW;        // [128][PADW]
    float* Hs = sm + 2 * CC * PADW;    // [128][PADW]  normalized h tile [c][s]

    int b = blockIdx.y, tile = blockIdx.x, t = threadIdx.x;
    int s0 = tile * TS;

    load_w_smem(WQ, wq, t);
    load_w_smem(WK, wk, t);
    {
        int c = t >> 2, q = t & 3;
        float scl = g_scale[b * CC + c], shf = g_shift[b * CC + c];
        const float4* src = reinterpret_cast<const float4*>(
            g_h + (size_t)(b * CC + c) * NKS + s0 + q * 32);
        float4* dst = reinterpret_cast<float4*>(Hs + c * PADW + q * 32);
#pragma unroll
        for (int i = 0; i < 8; i++) {
            float4 v = src[i];
            v.x = fmaxf(fmaf(v.x, scl, shf), 0.f);
            v.y = fmaxf(fmaf(v.y, scl, shf), 0.f);
            v.z = fmaxf(fmaf(v.z, scl, shf), 0.f);
            v.w = fmaxf(fmaf(v.w, scl, shf), 0.f);
            dst[i] = v;
        }
    }
    __syncthreads();

    int o0 = (t >> 3) * 2;
    int sb = (t & 7) * 16;

    float qa[2][16], ka[2][16];
#pragma unroll
    for (int j = 0; j < 16; j++) { qa[0][j] = 0.f; qa[1][j] = 0.f; ka[0][j] = 0.f; ka[1][j] = 0.f; }

#pragma unroll 2
    for (int c = 0; c < 128; c++) {
        float wq0 = WQ[o0 * PADW + c];
        float wq1 = WQ[o0 * PADW + PADW + c];
        float wk0 = WK[o0 * PADW + c];
        float wk1 = WK[o0 * PADW + PADW + c];
        float xr[16];
        const float4* hv = reinterpret_cast<const float4*>(Hs + c * PADW + sb);
        *reinterpret_cast<float4*>(&xr[0])  = hv[0];
        *reinterpret_cast<float4*>(&xr[4])  = hv[1];
        *reinterpret_cast<float4*>(&xr[8])  = hv[2];
        *reinterpret_cast<float4*>(&xr[12]) = hv[3];
#pragma unroll
        for (int j = 0; j < 16; j++) {
            qa[0][j] = fmaf(wq0, xr[j], qa[0][j]);
            qa[1][j] = fmaf(wq1, xr[j], qa[1][j]);
            ka[0][j] = fmaf(wk0, xr[j], ka[0][j]);
            ka[1][j] = fmaf(wk1, xr[j], ka[1][j]);
        }
    }

    // softmax over K=16 (register-local); qa[o][:] becomes exp weights
    float denom[2];
#pragma unroll
    for (int o = 0; o < 2; o++) {
        float bqv = bq[o0 + o], bkv = bk[o0 + o];
        float m = -1e30f;
#pragma unroll
        for (int j = 0; j < 16; j++) {
            float p = (qa[o][j] + bqv) * (ka[o][j] + bkv);
            qa[o][j] = p;
            m = fmaxf(m, p);
        }
        float d = 0.f;
#pragma unroll
        for (int j = 0; j < 16; j++) {
            float e = __expf(qa[o][j] - m);
            qa[o][j] = e;
            d += e;
        }
        denom[o] = d;
    }

    __syncthreads();
    load_w_smem(WQ, wv, t);      // reuse WQ buffer for Wv
    __syncthreads();

    // folded v: out[o,n] = bv + (1/denom) * sum_c Wv[o,c] * (sum_k e[k]*hn[c,k])
    float gg0 = 0.f, gg1 = 0.f;
#pragma unroll 2
    for (int c = 0; c < 128; c++) {
        float xr[16];
        const float4* hv = reinterpret_cast<const float4*>(Hs + c * PADW + sb);
        *reinterpret_cast<float4*>(&xr[0])  = hv[0];
        *reinterpret_cast<float4*>(&xr[4])  = hv[1];
        *reinterpret_cast<float4*>(&xr[8])  = hv[2];
        *reinterpret_cast<float4*>(&xr[12]) = hv[3];
        float d0 = 0.f, d1 = 0.f;
#pragma unroll
        for (int j = 0; j < 16; j++) {
            d0 = fmaf(qa[0][j], xr[j], d0);
            d1 = fmaf(qa[1][j], xr[j], d1);
        }
        gg0 = fmaf(WQ[o0 * PADW + c], d0, gg0);
        gg1 = fmaf(WQ[o0 * PADW + PADW + c], d1, gg1);
    }

    int n = tile * 8 + (t & 7);
    float gm = gamma1[0];
    {
        size_t i0 = (size_t)(b * CC + o0) * NN + n;
        size_t i1 = (size_t)(b * CC + o0 + 1) * NN + n;
        out[i0] = x_row[i0] + gm * (bv[o0]     + gg0 / denom[0]);
        out[i1] = x_row[i1] + gm * (bv[o0 + 1] + gg1 / denom[1]);
    }
}

// ---------------------------------------------------------------------------
extern "C" void kernel_launch(void* const* d_in, const int* in_sizes, int n_in,
                              void* d_out, int out_size) {
    const float* x_row   = (const float*)d_in[0];
    const float* x_local = (const float*)d_in[1];
    const float* w0      = (const float*)d_in[2];
    const float* b0      = (const float*)d_in[3];
    const float* bn_g    = (const float*)d_in[4];
    const float* bn_b    = (const float*)d_in[5];
    const float* wq      = (const float*)d_in[6];
    const float* bq      = (const float*)d_in[7];
    const float* wk      = (const float*)d_in[8];
    const float* bk      = (const float*)d_in[9];
    const float* wv      = (const float*)d_in[10];
    const float* bv      = (const float*)d_in[11];
    const float* gamma1  = (const float*)d_in[12];
    float* out = (float*)d_out;

    const int smemA = 2 * CC * PADW * (int)sizeof(float);   // 135168
    const int smemC = 3 * CC * PADW * (int)sizeof(float);   // 202752
    cudaFuncSetAttribute(k_conv0, cudaFuncAttributeMaxDynamicSharedMemorySize, smemA);
    cudaFuncSetAttribute(k_attn,  cudaFuncAttributeMaxDynamicSharedMemorySize, smemC);

    dim3 grid(TILES, BB);
    k_conv0<<<grid, 512, smemA>>>(x_local, w0, b0);
    k_stats<<<1, 1024>>>(bn_g, bn_b);
    k_attn<<<grid, 512, smemC>>>(x_row, wq, bq, wk, bk, wv, bv, gamma1, out);
}

// round 3
// speedup vs baseline: 1.1216x; 1.1216x over previous
#include <cuda_runtime.h>

#define BB    8
#define CC    128
#define NN    2000
#define KK    16
#define NKS   32000         // N*K spatial per (b,c)

// conv0 tiling
#define TS0   256
#define TILES0 125          // NKS / TS0
#define XS0   264           // Xs row stride (TS0 + 8 pad, mult of 4)
#define WS    132           // transposed weight row stride (128 + 4, mult of 4)

// attn tiling
#define TS1   128
#define TILES1 250          // NKS / TS1
#define QS    260           // Wqk row stride (256 + 4, mult of 4)
#define HS    132           // Hs row stride

typedef unsigned long long u64;

// Scratch (device globals: allocation-free rule)
__device__ __align__(16) float g_h[(size_t)BB * CC * NKS];   // conv0 output, 131MB
__device__ float g_psum[BB * TILES0 * CC];
__device__ float g_psq [BB * TILES0 * CC];
__device__ float g_scale[BB * CC];
__device__ float g_shift[BB * CC];

// ---- packed fp32x2 helpers (sm_103a) --------------------------------------
__device__ __forceinline__ void fma2(u64& d, u64 a, u64 b) {
    asm("fma.rn.f32x2 %0, %1, %2, %0;" : "+l"(d) : "l"(a), "l"(b));
}
__device__ __forceinline__ u64 pack2(float x, float y) {
    u64 r; asm("mov.b64 %0, {%1, %2};" : "=l"(r) : "f"(x), "f"(y)); return r;
}
__device__ __forceinline__ float2 unpack2(u64 v) {
    float2 r; asm("mov.b64 {%0, %1}, %2;" : "=f"(r.x), "=f"(r.y) : "l"(v)); return r;
}

__device__ __forceinline__ float red16(float v) {
    v += __shfl_xor_sync(0xffffffffu, v, 1);
    v += __shfl_xor_sync(0xffffffffu, v, 2);
    v += __shfl_xor_sync(0xffffffffu, v, 4);
    v += __shfl_xor_sync(0xffffffffu, v, 8);
    return v;
}

// ---------------------------------------------------------------------------
// Kernel 1: h = W0 @ x_local + b0  (+ per-tile partial sum/sumsq)
// grid (TILES0, BB), 512 thr. Thread = 4 out-channels x 16 spatial, f32x2.
// ---------------------------------------------------------------------------
__global__ __launch_bounds__(512) void k_conv0(const float* __restrict__ x,
                                               const float* __restrict__ w0,
                                               const float* __restrict__ b0) {
    extern __shared__ float sm[];
    float* Wt = sm;                  // [128][WS]  W0 transposed: Wt[c][o]
    float* Xs = sm + CC * WS;        // [128][XS0] x tile [c][s]

    int b = blockIdx.y, tile = blockIdx.x, t = threadIdx.x;
    int s0 = tile * TS0;

    // W0 [o][c] row-major -> Wt[c][o]
#pragma unroll
    for (int i = 0; i < 8; i++) {
        int f = i * 512 + t;             // float4 index 0..4095
        int o = f >> 5, c0 = (f & 31) << 2;
        float4 v = reinterpret_cast<const float4*>(w0)[f];
        Wt[(c0 + 0) * WS + o] = v.x;
        Wt[(c0 + 1) * WS + o] = v.y;
        Wt[(c0 + 2) * WS + o] = v.z;
        Wt[(c0 + 3) * WS + o] = v.w;
    }
    // X tile: 128 rows x 64 float4
    {
        int c = t >> 2, q = t & 3;
        const float4* src = reinterpret_cast<const float4*>(
            x + (size_t)(b * CC + c) * NKS + s0) + q * 16;
        float4* dst = reinterpret_cast<float4*>(Xs + c * XS0) + q * 16;
#pragma unroll
        for (int i = 0; i < 16; i++) dst[i] = src[i];
    }
    __syncthreads();

    int o0 = (t >> 4) * 4;       // 32 o-groups of 4
    int sb = (t & 15) * 16;      // 16 spatial groups of 16

    u64 acc[4][8];
#pragma unroll
    for (int o = 0; o < 4; o++)
#pragma unroll
        for (int j = 0; j < 8; j++) acc[o][j] = 0ull;

#pragma unroll 2
    for (int c = 0; c < 128; c++) {
        const ulonglong2* xv = reinterpret_cast<const ulonglong2*>(Xs + c * XS0 + sb);
        u64 xr[8];
        ulonglong2 p0 = xv[0], p1 = xv[1], p2 = xv[2], p3 = xv[3];
        xr[0] = p0.x; xr[1] = p0.y; xr[2] = p1.x; xr[3] = p1.y;
        xr[4] = p2.x; xr[5] = p2.y; xr[6] = p3.x; xr[7] = p3.y;
        float4 w4 = *reinterpret_cast<const float4*>(Wt + c * WS + o0);
        u64 wp0 = pack2(w4.x, w4.x), wp1 = pack2(w4.y, w4.y);
        u64 wp2 = pack2(w4.z, w4.z), wp3 = pack2(w4.w, w4.w);
#pragma unroll
        for (int j = 0; j < 8; j++) {
            fma2(acc[0][j], wp0, xr[j]);
            fma2(acc[1][j], wp1, xr[j]);
            fma2(acc[2][j], wp2, xr[j]);
            fma2(acc[3][j], wp3, xr[j]);
        }
    }

    float4 bias = *reinterpret_cast<const float4*>(b0 + o0);
    float bs[4] = { bias.x, bias.y, bias.z, bias.w };
#pragma unroll
    for (int o = 0; o < 4; o++) {
        float s = 0.f, sq = 0.f;
        float vr[16];
#pragma unroll
        for (int j = 0; j < 8; j++) {
            float2 p = unpack2(acc[o][j]);
            float v0 = p.x + bs[o], v1 = p.y + bs[o];
            vr[2 * j] = v0; vr[2 * j + 1] = v1;
            s += v0 + v1; sq += v0 * v0 + v1 * v1;
        }
        float4* dst = reinterpret_cast<float4*>(
            g_h + (size_t)(b * CC + o0 + o) * NKS + s0 + sb);
        dst[0] = *reinterpret_cast<float4*>(&vr[0]);
        dst[1] = *reinterpret_cast<float4*>(&vr[4]);
        dst[2] = *reinterpret_cast<float4*>(&vr[8]);
        dst[3] = *reinterpret_cast<float4*>(&vr[12]);
        s  = red16(s);
        sq = red16(sq);
        if ((t & 15) == 0) {
            int idx = (b * TILES0 + tile) * CC + o0 + o;
            g_psum[idx] = s;
            g_psq[idx]  = sq;
        }
    }
}

// ---------------------------------------------------------------------------
// Kernel 2: collapse IN + BN -> per-(b,c) affine. After IN, per-(b,c) mean==0
// and var==v/(v+eps_in); BN batch mean==0, BN var==mean_b[v/(v+eps_in)].
// ---------------------------------------------------------------------------
__global__ void k_stats(const float* __restrict__ bn_g, const float* __restrict__ bn_b) {
    __shared__ float rmat[BB][CC];
    __shared__ float bsc[CC];
    int t = threadIdx.x;
    int b = t >> 7, c = t & 127;

    float s = 0.f, q = 0.f;
    for (int i = 0; i < TILES0; i++) {
        int idx = (b * TILES0 + i) * CC + c;
        s += g_psum[idx];
        q += g_psq[idx];
    }
    const float inv_n = 1.0f / (float)NKS;
    float mu  = s * inv_n;
    float var = fmaxf(q * inv_n - mu * mu, 0.f);
    rmat[b][c] = var / (var + 1e-3f);
    __syncthreads();
    if (t < CC) {
        float ss = 0.f;
#pragma unroll
        for (int i = 0; i < BB; i++) ss += rmat[i][t];
        bsc[t] = rsqrtf(ss * (1.0f / BB) + 1e-5f);
    }
    __syncthreads();
    float scale = rsqrtf(var + 1e-3f) * bsc[c] * bn_g[c];
    g_scale[b * CC + c] = scale;
    g_shift[b * CC + c] = bn_b[c] - mu * scale;
}

// ---------------------------------------------------------------------------
// Kernel 3: hn = relu(affine(h)); fused q,k GEMM via interleaved Wqk;
// register softmax over K=16; folded v contraction; residual.
// grid (TILES1, BB), 512 thr. Thread = 2 channels x 1 n (16 k's).
// ---------------------------------------------------------------------------
__global__ __launch_bounds__(512) void k_attn(
    const float* __restrict__ x_row,
    const float* __restrict__ wq, const float* __restrict__ bq,
    const float* __restrict__ wk, const float* __restrict__ bk,
    const float* __restrict__ wv, const float* __restrict__ bv,
    const float* __restrict__ gamma1, float* __restrict__ out) {
    extern __shared__ float sm[];
    float* Wqk = sm;                 // [128][QS]: col 2o=wq[o], 2o+1=wk[o]; later Wvt[c][o]
    float* Hs  = sm + CC * QS;       // [128][HS]

    int b = blockIdx.y, tile = blockIdx.x, t = threadIdx.x;
    int s0 = tile * TS1;

    // interleave Wq/Wk transposed
#pragma unroll
    for (int i = 0; i < 8; i++) {
        int f = i * 512 + t;
        int o = f >> 5, c0 = (f & 31) << 2;
        float4 q4 = reinterpret_cast<const float4*>(wq)[f];
        float4 k4 = reinterpret_cast<const float4*>(wk)[f];
        Wqk[(c0 + 0) * QS + 2 * o]     = q4.x;
        Wqk[(c0 + 1) * QS + 2 * o]     = q4.y;
        Wqk[(c0 + 2) * QS + 2 * o]     = q4.z;
        Wqk[(c0 + 3) * QS + 2 * o]     = q4.w;
        Wqk[(c0 + 0) * QS + 2 * o + 1] = k4.x;
        Wqk[(c0 + 1) * QS + 2 * o + 1] = k4.y;
        Wqk[(c0 + 2) * QS + 2 * o + 1] = k4.z;
        Wqk[(c0 + 3) * QS + 2 * o + 1] = k4.w;
    }
    // normalized h tile
    {
        int c = t >> 2, q = t & 3;
        float scl = g_scale[b * CC + c], shf = g_shift[b * CC + c];
        const float4* src = reinterpret_cast<const float4*>(
            g_h + (size_t)(b * CC + c) * NKS + s0) + q * 8;
        float4* dst = reinterpret_cast<float4*>(Hs + c * HS) + q * 8;
#pragma unroll
        for (int i = 0; i < 8; i++) {
            float4 v = src[i];
            v.x = fmaxf(fmaf(v.x, scl, shf), 0.f);
            v.y = fmaxf(fmaf(v.y, scl, shf), 0.f);
            v.z = fmaxf(fmaf(v.z, scl, shf), 0.f);
            v.w = fmaxf(fmaf(v.w, scl, shf), 0.f);
            dst[i] = v;
        }
    }
    __syncthreads();

    int o0 = (t >> 3) * 2;       // 64 o-groups of 2
    int sb = (t & 7) * 16;       // 8 n per block

    u64 qa[2][8], ka[2][8];
#pragma unroll
    for (int j = 0; j < 8; j++) { qa[0][j] = 0ull; qa[1][j] = 0ull; ka[0][j] = 0ull; ka[1][j] = 0ull; }

#pragma unroll 2
    for (int c = 0; c < 128; c++) {
        const ulonglong2* xv = reinterpret_cast<const ulonglong2*>(Hs + c * HS + sb);
        u64 xr[8];
        ulonglong2 p0 = xv[0], p1 = xv[1], p2 = xv[2], p3 = xv[3];
        xr[0] = p0.x; xr[1] = p0.y; xr[2] = p1.x; xr[3] = p1.y;
        xr[4] = p2.x; xr[5] = p2.y; xr[6] = p3.x; xr[7] = p3.y;
        float4 w4 = *reinterpret_cast<const float4*>(Wqk + c * QS + 2 * o0);
        u64 wq0 = pack2(w4.x, w4.x), wk0 = pack2(w4.y, w4.y);
        u64 wq1 = pack2(w4.z, w4.z), wk1 = pack2(w4.w, w4.w);
#pragma unroll
        for (int j = 0; j < 8; j++) {
            fma2(qa[0][j], wq0, xr[j]);
            fma2(ka[0][j], wk0, xr[j]);
            fma2(qa[1][j], wq1, xr[j]);
            fma2(ka[1][j], wk1, xr[j]);
        }
    }

    // softmax over K=16; repack exp weights into qa[o][:]
    float denom[2];
#pragma unroll
    for (int o = 0; o < 2; o++) {
        float bqv = bq[o0 + o], bkv = bk[o0 + o];
        float p[16];
        float m = -1e30f;
#pragma unroll
        for (int j = 0; j < 8; j++) {
            float2 qv = unpack2(qa[o][j]);
            float2 kv = unpack2(ka[o][j]);
            float p0 = (qv.x + bqv) * (kv.x + bkv);
            float p1 = (qv.y + bqv) * (kv.y + bkv);
            p[2 * j] = p0; p[2 * j + 1] = p1;
            m = fmaxf(m, fmaxf(p0, p1));
        }
        float d = 0.f;
#pragma unroll
        for (int j = 0; j < 16; j++) {
            float e = __expf(p[j] - m);
            p[j] = e;
            d += e;
        }
        denom[o] = d;
#pragma unroll
        for (int j = 0; j < 8; j++) qa[o][j] = pack2(p[2 * j], p[2 * j + 1]);
    }

    __syncthreads();
    // overwrite Wqk region with transposed Wv (Wvt[c][o], stride HS=132)
#pragma unroll
    for (int i = 0; i < 8; i++) {
        int f = i * 512 + t;
        int o = f >> 5, c0 = (f & 31) << 2;
        float4 v4 = reinterpret_cast<const float4*>(wv)[f];
        Wqk[(c0 + 0) * HS + o] = v4.x;
        Wqk[(c0 + 1) * HS + o] = v4.y;
        Wqk[(c0 + 2) * HS + o] = v4.z;
        Wqk[(c0 + 3) * HS + o] = v4.w;
    }
    __syncthreads();

    // folded v: out[o,n] = bv + (1/denom) * sum_c Wv[o,c] * (sum_k e[k]*hn[c,k])
    float gg0 = 0.f, gg1 = 0.f;
#pragma unroll 2
    for (int c = 0; c < 128; c++) {
        const ulonglong2* xv = reinterpret_cast<const ulonglong2*>(Hs + c * HS + sb);
        u64 xr[8];
        ulonglong2 p0 = xv[0], p1 = xv[1], p2 = xv[2], p3 = xv[3];
        xr[0] = p0.x; xr[1] = p0.y; xr[2] = p1.x; xr[3] = p1.y;
        xr[4] = p2.x; xr[5] = p2.y; xr[6] = p3.x; xr[7] = p3.y;
        u64 d0 = 0ull, d1 = 0ull;
#pragma unroll
        for (int j = 0; j < 8; j++) {
            fma2(d0, qa[0][j], xr[j]);
            fma2(d1, qa[1][j], xr[j]);
        }
        float2 wv2 = *reinterpret_cast<const float2*>(Wqk + c * HS + o0);
        float2 s0v = unpack2(d0), s1v = unpack2(d1);
        gg0 = fmaf(wv2.x, s0v.x + s0v.y, gg0);
        gg1 = fmaf(wv2.y, s1v.x + s1v.y, gg1);
    }

    int n = tile * 8 + (t & 7);
    float gm = gamma1[0];
    {
        size_t i0 = (size_t)(b * CC + o0) * NN + n;
        size_t i1 = (size_t)(b * CC + o0 + 1) * NN + n;
        out[i0] = x_row[i0] + gm * (bv[o0]     + gg0 / denom[0]);
        out[i1] = x_row[i1] + gm * (bv[o0 + 1] + gg1 / denom[1]);
    }
}

// ---------------------------------------------------------------------------
extern "C" void kernel_launch(void* const* d_in, const int* in_sizes, int n_in,
                              void* d_out, int out_size) {
    const float* x_row   = (const float*)d_in[0];
    const float* x_local = (const float*)d_in[1];
    const float* w0      = (const float*)d_in[2];
    const float* b0      = (const float*)d_in[3];
    const float* bn_g    = (const float*)d_in[4];
    const float* bn_b    = (const float*)d_in[5];
    const float* wq      = (const float*)d_in[6];
    const float* bq      = (const float*)d_in[7];
    const float* wk      = (const float*)d_in[8];
    const float* bk      = (const float*)d_in[9];
    const float* wv      = (const float*)d_in[10];
    const float* bv      = (const float*)d_in[11];
    const float* gamma1  = (const float*)d_in[12];
    float* out = (float*)d_out;

    const int smemA = (CC * WS + CC * XS0) * (int)sizeof(float);  // 202752
    const int smemC = (CC * QS + CC * HS) * (int)sizeof(float);   // 200704
    cudaFuncSetAttribute(k_conv0, cudaFuncAttributeMaxDynamicSharedMemorySize, smemA);
    cudaFuncSetAttribute(k_attn,  cudaFuncAttributeMaxDynamicSharedMemorySize, smemC);

    k_conv0<<<dim3(TILES0, BB), 512, smemA>>>(x_local, w0, b0);
    k_stats<<<1, 1024>>>(bn_g, bn_b);
    k_attn<<<dim3(TILES1, BB), 512, smemC>>>(x_row, wq, bq, wk, bk, wv, bv, gamma1, out);
}

// round 5
// speedup vs baseline: 3.4553x; 3.0806x over previous
#include <cuda_runtime.h>

#define BB    8
#define CC    128
#define NN    2000
#define KK    16
#define NKS   32000         // N*K spatial per (b,c)

// conv0 tiling: block = 128 o x 256 s, thread = 8 o x 8 s
#define TS0   256
#define TILES0 125          // NKS / TS0
#define XS0   260           // Xs row stride floats (64 chunks * 4 + 4 pad)
#define WS    132           // transposed weight row stride

// attn tiling: block = 128 o x 128 s, thread = 4 o x 8 s
#define TS1   128
#define TILES1 250          // NKS / TS1
#define QS    260           // Wqk row stride (256 + 4)
#define HS    132           // Hs row stride (128 + 4)

typedef unsigned long long u64;

// Scratch (device globals: allocation-free rule)
__device__ __align__(16) float g_h[(size_t)BB * CC * NKS];   // conv0 output, 131MB
__device__ float g_psum[BB * TILES0 * CC];
__device__ float g_psq [BB * TILES0 * CC];
__device__ float g_scale[BB * CC];
__device__ float g_shift[BB * CC];

// ---- packed fp32x2 helpers (sm_103a) --------------------------------------
__device__ __forceinline__ void fma2(u64& d, u64 a, u64 b) {
    asm("fma.rn.f32x2 %0, %1, %2, %0;" : "+l"(d) : "l"(a), "l"(b));
}
__device__ __forceinline__ u64 pack2(float x, float y) {
    u64 r; asm("mov.b64 %0, {%1, %2};" : "=l"(r) : "f"(x), "f"(y)); return r;
}
__device__ __forceinline__ float2 unpack2(u64 v) {
    float2 r; asm("mov.b64 {%0, %1}, %2;" : "=f"(r.x), "=f"(r.y) : "l"(v)); return r;
}
__device__ __forceinline__ float red32(float v) {
#pragma unroll
    for (int m = 16; m; m >>= 1) v += __shfl_xor_sync(0xffffffffu, v, m);
    return v;
}

// ---------------------------------------------------------------------------
// Kernel 1: h = W0 @ x_local + b0  (+ per-tile partial sum/sumsq)
// grid (TILES0, BB), 512 thr. Thread = 8 out-channels x 8 spatial, f32x2.
// Xs chunk layout permuted: chunk j (16B) stored at p(j) = (j&1)*32 + (j>>1),
// so the mainloop's per-thread reads are lane-consecutive -> conflict-free.
// ---------------------------------------------------------------------------
__global__ __launch_bounds__(512) void k_conv0(const float* __restrict__ x,
                                               const float* __restrict__ w0,
                                               const float* __restrict__ b0) {
    extern __shared__ float sm[];
    float* Wt = sm;                  // [128][WS]  W0 transposed: Wt[c][o]
    float* Xs = sm + CC * WS;        // [128][XS0] permuted x tile

    int b = blockIdx.y, tile = blockIdx.x, t = threadIdx.x;
    int s0 = tile * TS0;

    // W0 [o][c] -> Wt[c][o]
#pragma unroll
    for (int i = 0; i < 8; i++) {
        int f = i * 512 + t;
        int o = f >> 5, c0 = (f & 31) << 2;
        float4 v = reinterpret_cast<const float4*>(w0)[f];
        Wt[(c0 + 0) * WS + o] = v.x;
        Wt[(c0 + 1) * WS + o] = v.y;
        Wt[(c0 + 2) * WS + o] = v.z;
        Wt[(c0 + 3) * WS + o] = v.w;
    }
    // X tile, permuted-contiguous stores (conflict-free)
    {
        int qp = t & 15, cb = t >> 4;         // 16 col-threads x 32 rows
#pragma unroll
        for (int pass = 0; pass < 4; pass++) {
            int c = cb + 32 * pass;
            const float* src = x + (size_t)(b * CC + c) * NKS + s0;
            float* dst = Xs + c * XS0;
#pragma unroll
            for (int i = 0; i < 4; i++) {
                int p = qp + 16 * i;                  // permuted chunk 0..63
                int j = 2 * (p & 31) + (p >> 5);      // original chunk
                *reinterpret_cast<float4*>(dst + p * 4) =
                    *reinterpret_cast<const float4*>(src + j * 4);
            }
        }
    }
    __syncthreads();

    int o0 = (t >> 5) * 8;       // 16 o-groups of 8 (constant per warp)
    int u  = t & 31;             // 32 s-groups of 8; s = 8u..8u+7

    u64 acc[8][4];
#pragma unroll
    for (int o = 0; o < 8; o++)
#pragma unroll
        for (int j = 0; j < 4; j++) acc[o][j] = 0ull;

    for (int c = 0; c < 128; c++) {
        const float* xrow = Xs + c * XS0;
        ulonglong2 xa = *reinterpret_cast<const ulonglong2*>(xrow + u * 4);
        ulonglong2 xb = *reinterpret_cast<const ulonglong2*>(xrow + (32 + u) * 4);
        u64 xr[4] = { xa.x, xa.y, xb.x, xb.y };
        float4 wA = *reinterpret_cast<const float4*>(Wt + c * WS + o0);
        float4 wB = *reinterpret_cast<const float4*>(Wt + c * WS + o0 + 4);
        u64 wp[8] = { pack2(wA.x, wA.x), pack2(wA.y, wA.y),
                      pack2(wA.z, wA.z), pack2(wA.w, wA.w),
                      pack2(wB.x, wB.x), pack2(wB.y, wB.y),
                      pack2(wB.z, wB.z), pack2(wB.w, wB.w) };
#pragma unroll
        for (int o = 0; o < 8; o++)
#pragma unroll
            for (int j = 0; j < 4; j++) fma2(acc[o][j], wp[o], xr[j]);
    }

    float4 bA = *reinterpret_cast<const float4*>(b0 + o0);
    float4 bB = *reinterpret_cast<const float4*>(b0 + o0 + 4);
    float bs[8] = { bA.x, bA.y, bA.z, bA.w, bB.x, bB.y, bB.z, bB.w };
    int lane = t & 31;
#pragma unroll
    for (int o = 0; o < 8; o++) {
        float vr[8];
        float s = 0.f, sq = 0.f;
#pragma unroll
        for (int j = 0; j < 4; j++) {
            float2 p = unpack2(acc[o][j]);
            float v0 = p.x + bs[o], v1 = p.y + bs[o];
            vr[2 * j] = v0; vr[2 * j + 1] = v1;
            s += v0 + v1; sq += v0 * v0 + v1 * v1;
        }
        float4* dst = reinterpret_cast<float4*>(
            g_h + (size_t)(b * CC + o0 + o) * NKS + s0 + 8 * u);
        dst[0] = *reinterpret_cast<float4*>(&vr[0]);
        dst[1] = *reinterpret_cast<float4*>(&vr[4]);
        s  = red32(s);
        sq = red32(sq);
        if (lane == 0) {
            int idx = (b * TILES0 + tile) * CC + o0 + o;
            g_psum[idx] = s;
            g_psq[idx]  = sq;
        }
    }
}

// ---------------------------------------------------------------------------
// Kernel 2: collapse IN + BN -> per-(b,c) affine. After IN, per-(b,c) mean==0
// and var==v/(v+eps_in); BN batch mean==0, BN var==mean_b[v/(v+eps_in)].
// ---------------------------------------------------------------------------
__global__ void k_stats(const float* __restrict__ bn_g, const float* __restrict__ bn_b) {
    __shared__ float rmat[BB][CC];
    __shared__ float bsc[CC];
    int t = threadIdx.x;
    int b = t >> 7, c = t & 127;

    float s = 0.f, q = 0.f;
    for (int i = 0; i < TILES0; i++) {
        int idx = (b * TILES0 + i) * CC + c;
        s += g_psum[idx];
        q += g_psq[idx];
    }
    const float inv_n = 1.0f / (float)NKS;
    float mu  = s * inv_n;
    float var = fmaxf(q * inv_n - mu * mu, 0.f);
    rmat[b][c] = var / (var + 1e-3f);
    __syncthreads();
    if (t < CC) {
        float ss = 0.f;
#pragma unroll
        for (int i = 0; i < BB; i++) ss += rmat[i][t];
        bsc[t] = rsqrtf(ss * (1.0f / BB) + 1e-5f);
    }
    __syncthreads();
    float scale = rsqrtf(var + 1e-3f) * bsc[c] * bn_g[c];
    g_scale[b * CC + c] = scale;
    g_shift[b * CC + c] = bn_b[c] - mu * scale;
}

// ---------------------------------------------------------------------------
// Kernel 3: hn = relu(affine(h)); fused q,k GEMM; softmax over K=16 split
// across lane pairs (shfl_xor 1); folded v contraction; residual.
// grid (TILES1, BB), 512 thr. Thread = 4 channels x 8 spatial.
// Hs chunk layout permuted: p(j) = (j&1)*16 + (j>>1)  -> conflict-free reads.
// ---------------------------------------------------------------------------
__global__ __launch_bounds__(512) void k_attn(
    const float* __restrict__ x_row,
    const float* __restrict__ wq, const float* __restrict__ bq,
    const float* __restrict__ wk, const float* __restrict__ bk,
    const float* __restrict__ wv, const float* __restrict__ bv,
    const float* __restrict__ gamma1, float* __restrict__ out) {
    extern __shared__ float sm[];
    float* Wqk = sm;                 // [128][QS] interleaved wq/wk; later Wvt
    float* Hs  = sm + CC * QS;       // [128][HS] permuted normalized h tile

    int b = blockIdx.y, tile = blockIdx.x, t = threadIdx.x;
    int s0 = tile * TS1;

    // interleave Wq/Wk transposed: Wqk[c][2o]=wq[o][c], [2o+1]=wk[o][c]
#pragma unroll
    for (int i = 0; i < 8; i++) {
        int f = i * 512 + t;
        int o = f >> 5, c0 = (f & 31) << 2;
        float4 q4 = reinterpret_cast<const float4*>(wq)[f];
        float4 k4 = reinterpret_cast<const float4*>(wk)[f];
        Wqk[(c0 + 0) * QS + 2 * o]     = q4.x;
        Wqk[(c0 + 1) * QS + 2 * o]     = q4.y;
        Wqk[(c0 + 2) * QS + 2 * o]     = q4.z;
        Wqk[(c0 + 3) * QS + 2 * o]     = q4.w;
        Wqk[(c0 + 0) * QS + 2 * o + 1] = k4.x;
        Wqk[(c0 + 1) * QS + 2 * o + 1] = k4.y;
        Wqk[(c0 + 2) * QS + 2 * o + 1] = k4.z;
        Wqk[(c0 + 3) * QS + 2 * o + 1] = k4.w;
    }
    // normalized h tile, permuted-contiguous stores
    {
        int qp = t & 15, cb = t >> 4;
#pragma unroll
        for (int pass = 0; pass < 4; pass++) {
            int c = cb + 32 * pass;
            float scl = g_scale[b * CC + c], shf = g_shift[b * CC + c];
            const float* src = g_h + (size_t)(b * CC + c) * NKS + s0;
            float* dst = Hs + c * HS;
#pragma unroll
            for (int i = 0; i < 2; i++) {
                int p = qp + 16 * i;                 // permuted chunk 0..31
                int j = 2 * (p & 15) + (p >> 4);     // original chunk
                float4 v = *reinterpret_cast<const float4*>(src + j * 4);
                v.x = fmaxf(fmaf(v.x, scl, shf), 0.f);
                v.y = fmaxf(fmaf(v.y, scl, shf), 0.f);
                v.z = fmaxf(fmaf(v.z, scl, shf), 0.f);
                v.w = fmaxf(fmaf(v.w, scl, shf), 0.f);
                *reinterpret_cast<float4*>(dst + p * 4) = v;
            }
        }
    }
    __syncthreads();

    int o0 = (t >> 4) * 4;       // 32 o-groups of 4
    int u  = t & 15;             // 16 s-groups of 8; s = 8u..8u+7

    u64 qa[4][4], ka[4][4];
#pragma unroll
    for (int o = 0; o < 4; o++)
#pragma unroll
        for (int j = 0; j < 4; j++) { qa[o][j] = 0ull; ka[o][j] = 0ull; }

    for (int c = 0; c < 128; c++) {
        const float* xrow = Hs + c * HS;
        ulonglong2 xa = *reinterpret_cast<const ulonglong2*>(xrow + u * 4);
        ulonglong2 xb = *reinterpret_cast<const ulonglong2*>(xrow + (16 + u) * 4);
        u64 xr[4] = { xa.x, xa.y, xb.x, xb.y };
        float4 wA = *reinterpret_cast<const float4*>(Wqk + c * QS + 2 * o0);
        float4 wB = *reinterpret_cast<const float4*>(Wqk + c * QS + 2 * o0 + 4);
        u64 wqp[4] = { pack2(wA.x, wA.x), pack2(wA.z, wA.z),
                       pack2(wB.x, wB.x), pack2(wB.z, wB.z) };
        u64 wkp[4] = { pack2(wA.y, wA.y), pack2(wA.w, wA.w),
                       pack2(wB.y, wB.y), pack2(wB.w, wB.w) };
#pragma unroll
        for (int o = 0; o < 4; o++)
#pragma unroll
            for (int j = 0; j < 4; j++) {
                fma2(qa[o][j], wqp[o], xr[j]);
                fma2(ka[o][j], wkp[o], xr[j]);
            }
    }

    // softmax over K=16, split across lane pairs (u even: k0..7, u odd: k8..15)
    float denom[4];
#pragma unroll
    for (int o = 0; o < 4; o++) {
        float bqv = bq[o0 + o], bkv = bk[o0 + o];
        float p[8];
        float m = -1e30f;
#pragma unroll
        for (int j = 0; j < 4; j++) {
            float2 qv = unpack2(qa[o][j]);
            float2 kv = unpack2(ka[o][j]);
            float p0 = (qv.x + bqv) * (kv.x + bkv);
            float p1 = (qv.y + bqv) * (kv.y + bkv);
            p[2 * j] = p0; p[2 * j + 1] = p1;
            m = fmaxf(m, fmaxf(p0, p1));
        }
        m = fmaxf(m, __shfl_xor_sync(0xffffffffu, m, 1));
        float d = 0.f;
#pragma unroll
        for (int j = 0; j < 8; j++) {
            float e = __expf(p[j] - m);
            p[j] = e;
            d += e;
        }
        d += __shfl_xor_sync(0xffffffffu, d, 1);
        denom[o] = d;
#pragma unroll
        for (int j = 0; j < 4; j++) qa[o][j] = pack2(p[2 * j], p[2 * j + 1]);
    }

    __syncthreads();
    // overwrite Wqk region with transposed Wv (Wvt[c][o], stride HS=132)
#pragma unroll
    for (int i = 0; i < 8; i++) {
        int f = i * 512 + t;
        int o = f >> 5, c0 = (f & 31) << 2;
        float4 v4 = reinterpret_cast<const float4*>(wv)[f];
        Wqk[(c0 + 0) * HS + o] = v4.x;
        Wqk[(c0 + 1) * HS + o] = v4.y;
        Wqk[(c0 + 2) * HS + o] = v4.z;
        Wqk[(c0 + 3) * HS + o] = v4.w;
    }
    __syncthreads();

    // folded v: partial over this lane's 8 k's; partner lane adds the rest
    u64 gv[4];
#pragma unroll
    for (int o = 0; o < 4; o++) gv[o] = 0ull;

    for (int c = 0; c < 128; c++) {
        const float* xrow = Hs + c * HS;
        ulonglong2 xa = *reinterpret_cast<const ulonglong2*>(xrow + u * 4);
        ulonglong2 xb = *reinterpret_cast<const ulonglong2*>(xrow + (16 + u) * 4);
        u64 xr[4] = { xa.x, xa.y, xb.x, xb.y };
        float4 wv4 = *reinterpret_cast<const float4*>(Wqk + c * HS + o0);
        float wvs[4] = { wv4.x, wv4.y, wv4.z, wv4.w };
#pragma unroll
        for (int o = 0; o < 4; o++) {
            u64 d = 0ull;
#pragma unroll
            for (int j = 0; j < 4; j++) fma2(d, qa[o][j], xr[j]);
            fma2(gv[o], pack2(wvs[o], wvs[o]), d);
        }
    }

    float gm = gamma1[0];
#pragma unroll
    for (int o = 0; o < 4; o++) {
        float2 g2 = unpack2(gv[o]);
        float gg = g2.x + g2.y;
        gg += __shfl_xor_sync(0xffffffffu, gg, 1);
        if ((u & 1) == 0) {
            int n = tile * 8 + (u >> 1);
            size_t idx = (size_t)(b * CC + o0 + o) * NN + n;
            out[idx] = x_row[idx] + gm * (bv[o0 + o] + gg / denom[o]);
        }
    }
}

// ---------------------------------------------------------------------------
extern "C" void kernel_launch(void* const* d_in, const int* in_sizes, int n_in,
                              void* d_out, int out_size) {
    const float* x_row   = (const float*)d_in[0];
    const float* x_local = (const float*)d_in[1];
    const float* w0      = (const float*)d_in[2];
    const float* b0      = (const float*)d_in[3];
    const float* bn_g    = (const float*)d_in[4];
    const float* bn_b    = (const float*)d_in[5];
    const float* wq      = (const float*)d_in[6];
    const float* bq      = (const float*)d_in[7];
    const float* wk      = (const float*)d_in[8];
    const float* bk      = (const float*)d_in[9];
    const float* wv      = (const float*)d_in[10];
    const float* bv      = (const float*)d_in[11];
    const float* gamma1  = (const float*)d_in[12];
    float* out = (float*)d_out;

    const int smemA = (CC * WS + CC * XS0) * (int)sizeof(float);  // 200704
    const int smemC = (CC * QS + CC * HS) * (int)sizeof(float);   // 200704
    cudaFuncSetAttribute(k_conv0, cudaFuncAttributeMaxDynamicSharedMemorySize, smemA);
    cudaFuncSetAttribute(k_attn,  cudaFuncAttributeMaxDynamicSharedMemorySize, smemC);

    k_conv0<<<dim3(TILES0, BB), 512, smemA>>>(x_local, w0, b0);
    k_stats<<<1, 1024>>>(bn_g, bn_b);
    k_attn<<<dim3(TILES1, BB), 512, smemC>>>(x_row, wq, bq, wk, bk, wv, bv, gamma1, out);
}

// round 12
// speedup vs baseline: 6.4500x; 1.8667x over previous
#include <cuda_runtime.h>
#include <cuda_bf16.h>

typedef unsigned int u32;
typedef unsigned long long u64;

#define BB   8
#define CC   128
#define NN   2000
#define NKS  32000
#define TIL  250          // s-tiles of 128 per batch
#define TSI  128

#define TILE_B 32768      // one 128x128 bf16 tile (256B pitch)

// conv0 smem offsets
#define C_WH   0
#define C_WL   (1 * TILE_B)
#define C_XH   (2 * TILE_B)
#define C_XL   (3 * TILE_B)
#define C_BUF  (4 * TILE_B)              // fp32 [128][132] = 67584
#define C_S4   (4 * TILE_B + 67584)      // fp32 [2][4][128] = 4096
#define C_SMEM (4 * TILE_B + 67584 + 4096)

// k_attn smem offsets
#define A_QH   0
#define A_QL   (1 * TILE_B)
#define A_KH   (2 * TILE_B)
#define A_KL   (3 * TILE_B)
#define A_HH   (4 * TILE_B)
#define A_HL   (5 * TILE_B)
#define A_SMEM (6 * TILE_B)

// Scratch (device globals: allocation-free rule)
__device__ __align__(16) float g_h[(size_t)BB * NKS * CC];   // h as [b][s][c]
__device__ float g_psum[BB * TIL * CC];
__device__ float g_psq [BB * TIL * CC];
__device__ __align__(16) float g_scale[BB * CC];
__device__ __align__(16) float g_shift[BB * CC];

// ---------------------------------------------------------------------------
// helpers
// ---------------------------------------------------------------------------
__device__ __forceinline__ u32 smem_u32(const void* p) {
    u32 a;
    asm("{ .reg .u64 t; cvta.to.shared.u64 t, %1; cvt.u32.u64 %0, t; }" : "=r"(a) : "l"(p));
    return a;
}

// a -> low half, b -> high half; hi/lo bf16 split of the fp32 pair
__device__ __forceinline__ void split2(float a, float b, u32& hi, u32& lo) {
    u32 h;
    asm("cvt.rn.bf16x2.f32 %0, %1, %2;" : "=r"(h) : "f"(b), "f"(a));
    float fa = __uint_as_float(h << 16);
    float fb = __uint_as_float(h & 0xffff0000u);
    float la = a - fa, lb = b - fb;
    asm("cvt.rn.bf16x2.f32 %0, %1, %2;" : "=r"(lo) : "f"(lb), "f"(la));
    hi = h;
}

__device__ __forceinline__ void ldsm4(u32 r[4], u32 addr) {
    asm volatile("ldmatrix.sync.aligned.m8n8.x4.shared.b16 {%0,%1,%2,%3}, [%4];"
        : "=r"(r[0]), "=r"(r[1]), "=r"(r[2]), "=r"(r[3]) : "r"(addr));
}
__device__ __forceinline__ void ldsm4t(u32 r[4], u32 addr) {
    asm volatile("ldmatrix.sync.aligned.m8n8.x4.trans.shared.b16 {%0,%1,%2,%3}, [%4];"
        : "=r"(r[0]), "=r"(r[1]), "=r"(r[2]), "=r"(r[3]) : "r"(addr));
}
__device__ __forceinline__ void mma16816(float d[4], const u32 a[4], const u32 b[2]) {
    asm volatile("mma.sync.aligned.m16n8k16.row.col.f32.bf16.bf16.f32 "
        "{%0,%1,%2,%3}, {%4,%5,%6,%7}, {%8,%9}, {%0,%1,%2,%3};"
        : "+f"(d[0]), "+f"(d[1]), "+f"(d[2]), "+f"(d[3])
        : "r"(a[0]), "r"(a[1]), "r"(a[2]), "r"(a[3]), "r"(b[0]), "r"(b[1]));
}

// Stage 128x128 fp32 row-major matrix into hi/lo bf16 tiles, 256B pitch,
// chunk-swizzled (XOR row%8 into 16B-chunk index). 512 threads, coalesced.
__device__ __forceinline__ void stage_w(char* smc, int offHi, int offLo,
                                        const float* __restrict__ w, int t) {
#pragma unroll
    for (int i = 0; i < 8; i++) {
        int f = i * 512 + t;
        int o = f >> 5, c0 = (f & 31) << 2;
        float4 v = reinterpret_cast<const float4*>(w)[f];
        u32 h0, l0, h1, l1;
        split2(v.x, v.y, h0, l0);
        split2(v.z, v.w, h1, l1);
        u32 ad = (u32)(o * 256) + (u32)((c0 * 2) ^ ((o & 7) << 4));
        *reinterpret_cast<u64*>(smc + offHi + ad) = ((u64)h1 << 32) | h0;
        *reinterpret_cast<u64*>(smc + offLo + ad) = ((u64)l1 << 32) | l0;
    }
}

// ---------------------------------------------------------------------------
// Kernel 1: h = W0 @ x + b0 via mma.sync (bf16-split), h stored [b][s][c];
// per-tile partial sum/sumsq. grid (250, 8), 512 threads.
// ---------------------------------------------------------------------------
__global__ __launch_bounds__(512, 1) void k_conv0(const float* __restrict__ x,
                                                  const float* __restrict__ w0,
                                                  const float* __restrict__ b0) {
    extern __shared__ char smc[];
    u32 sm32 = smem_u32(smc);
    int t = threadIdx.x, wid = t >> 5, L = t & 31;
    int b = blockIdx.y, tile = blockIdx.x;
    int s0 = tile * TSI;

    // A = W0 [o][c] hi/lo
    stage_w(smc, C_WH, C_WL, w0, t);

    // B = x tile, natural [c][s] layout (row=c, col=s); pairs along s in-thread
    {
        int c = t >> 2, sb = (t & 3) * 32;
        const float4* src = reinterpret_cast<const float4*>(
            x + ((size_t)b * CC + c) * NKS + s0 + sb);
        u32 rowbase = (u32)(c * 256);
        u32 xm = (u32)((c & 7) << 4);
#pragma unroll
        for (int i = 0; i < 8; i++) {
            float4 v = src[i];
            u32 h0, l0, h1, l1;
            split2(v.x, v.y, h0, l0);
            split2(v.z, v.w, h1, l1);
            u32 ad = rowbase + (((u32)(sb * 2 + i * 8)) ^ xm);
            *reinterpret_cast<u64*>(smc + C_XH + ad) = ((u64)h1 << 32) | h0;
            *reinterpret_cast<u64*>(smc + C_XL + ad) = ((u64)l1 << 32) | l0;
        }
    }
    __syncthreads();

    int obase = (wid & 3) * 32, sbase = (wid >> 2) * 32;
    int m = L >> 3;
    int rA_off = (m & 1) * 8 + (L & 7);   // A row offset within 16
    int kbA_off = (m >> 1) * 16;          // A k-byte offset
    int krB_off = (m & 1) * 8 + (L & 7);  // B (trans) k-row offset within 16
    int cbB = sbase * 2 + (m >> 1) * 16;  // B col-byte base

    float d[2][4][4];
#pragma unroll
    for (int mf = 0; mf < 2; mf++)
#pragma unroll
        for (int nf = 0; nf < 4; nf++)
#pragma unroll
            for (int j = 0; j < 4; j++) d[mf][nf][j] = 0.f;

#pragma unroll
    for (int ks = 0; ks < 8; ks++) {
        u32 bh[4][2], bl[4][2];
        int krow = ks * 16 + krB_off;
        u32 rowb = (u32)(krow * 256);
        u32 xm = (u32)((krow & 7) << 4);
#pragma unroll
        for (int np = 0; np < 2; np++) {
            u32 ad = rowb + (((u32)(cbB + np * 32)) ^ xm);
            u32 r[4];
            ldsm4t(r, sm32 + C_XH + ad);
            bh[np * 2][0] = r[0]; bh[np * 2][1] = r[1];
            bh[np * 2 + 1][0] = r[2]; bh[np * 2 + 1][1] = r[3];
            ldsm4t(r, sm32 + C_XL + ad);
            bl[np * 2][0] = r[0]; bl[np * 2][1] = r[1];
            bl[np * 2 + 1][0] = r[2]; bl[np * 2 + 1][1] = r[3];
        }
        u32 ah[2][4], al[2][4];
#pragma unroll
        for (int mf = 0; mf < 2; mf++) {
            int row = obase + mf * 16 + rA_off;
            u32 ad = (u32)(row * 256) + (u32)((ks * 32 + kbA_off) ^ ((row & 7) << 4));
            ldsm4(ah[mf], sm32 + C_WH + ad);
            ldsm4(al[mf], sm32 + C_WL + ad);
        }
#pragma unroll
        for (int mf = 0; mf < 2; mf++)
#pragma unroll
            for (int nf = 0; nf < 4; nf++) {
                mma16816(d[mf][nf], ah[mf], bh[nf]);
                mma16816(d[mf][nf], ah[mf], bl[nf]);
                mma16816(d[mf][nf], al[mf], bh[nf]);
            }
    }

    // stage D[o][s] -> buf[s][o] (pitch 132, conflict-free pattern)
    float* buf = reinterpret_cast<float*>(smc + C_BUF);
#pragma unroll
    for (int mf = 0; mf < 2; mf++)
#pragma unroll
        for (int nf = 0; nf < 4; nf++)
#pragma unroll
            for (int j = 0; j < 4; j++) {
                int srow = sbase + nf * 8 + (L & 3) * 2 + (j & 1);
                int o = obase + mf * 16 + (L >> 2) + (j >> 1) * 8;
                buf[srow * 132 + o] = d[mf][nf][j];
            }
    __syncthreads();

    // read buf rows, add bias, write g_h[b][s][c] coalesced + stats partials
    {
        float* s4 = reinterpret_cast<float*>(smc + C_S4);
        int c = t & 127, sq = t >> 7;
        float bias = b0[c];
        float sacc = 0.f, qacc = 0.f;
#pragma unroll 4
        for (int i = 0; i < 32; i++) {
            int srow = sq * 32 + i;
            float v = buf[srow * 132 + c] + bias;
            g_h[((size_t)b * NKS + s0 + srow) * CC + c] = v;
            sacc += v; qacc += v * v;
        }
        s4[sq * 128 + c] = sacc;
        s4[512 + sq * 128 + c] = qacc;
        __syncthreads();
        if (t < 128) {
            float s = s4[t] + s4[128 + t] + s4[256 + t] + s4[384 + t];
            float q = s4[512 + t] + s4[640 + t] + s4[768 + t] + s4[896 + t];
            int pi = (b * TIL + tile) * CC + t;
            g_psum[pi] = s;
            g_psq[pi] = q;
        }
    }
}

// ---------------------------------------------------------------------------
// Kernel 2: collapse IN + BN -> per-(b,c) affine. After IN, per-(b,c) mean==0
// and var==v/(v+eps_in); BN batch mean==0, BN var==mean_b[v/(v+eps_in)].
// ---------------------------------------------------------------------------
__global__ void k_stats(const float* __restrict__ bn_g, const float* __restrict__ bn_b) {
    __shared__ float rmat[BB][CC];
    __shared__ float bsc[CC];
    int t = threadIdx.x;
    int b = t >> 7, c = t & 127;

    float s = 0.f, q = 0.f;
    for (int i = 0; i < TIL; i++) {
        int idx = (b * TIL + i) * CC + c;
        s += g_psum[idx];
        q += g_psq[idx];
    }
    const float inv_n = 1.0f / (float)NKS;
    float mu  = s * inv_n;
    float var = fmaxf(q * inv_n - mu * mu, 0.f);
    rmat[b][c] = var / (var + 1e-3f);
    __syncthreads();
    if (t < CC) {
        float ss = 0.f;
#pragma unroll
        for (int i = 0; i < BB; i++) ss += rmat[i][t];
        bsc[t] = rsqrtf(ss * (1.0f / BB) + 1e-5f);
    }
    __syncthreads();
    float scale = rsqrtf(var + 1e-3f) * bsc[c] * bn_g[c];
    g_scale[b * CC + c] = scale;
    g_shift[b * CC + c] = bn_b[c] - mu * scale;
}

// ---------------------------------------------------------------------------
// Kernel 3: hn = relu(affine(h)); q,k,v GEMMs via mma.sync (bf16-split);
// softmax over K=16 via quad shfl; residual. grid (250, 8), 512 threads.
// ---------------------------------------------------------------------------
__global__ __launch_bounds__(512, 1) void k_attn(
    const float* __restrict__ x_row,
    const float* __restrict__ wq, const float* __restrict__ bq,
    const float* __restrict__ wk, const float* __restrict__ bk,
    const float* __restrict__ wv, const float* __restrict__ bv,
    const float* __restrict__ gamma1, float* __restrict__ out) {
    extern __shared__ char smc[];
    u32 sm32 = smem_u32(smc);
    int t = threadIdx.x, wid = t >> 5, L = t & 31;
    int b = blockIdx.y, tile = blockIdx.x;
    int s0 = tile * TSI;

    stage_w(smc, A_QH, A_QL, wq, t);
    stage_w(smc, A_KH, A_KL, wk, t);

    // B = hn tile [s][c]: read g_h[b][s][c], affine+relu, split, swizzled store
    {
        int srow = t >> 2, cb = (t & 3) * 32;
        const float4* hp  = reinterpret_cast<const float4*>(
            g_h + ((size_t)b * NKS + s0 + srow) * CC + cb);
        const float4* scp = reinterpret_cast<const float4*>(g_scale + b * CC + cb);
        const float4* shp = reinterpret_cast<const float4*>(g_shift + b * CC + cb);
        u32 rowb = (u32)(srow * 256);
        u32 xm = (u32)((srow & 7) << 4);
#pragma unroll
        for (int i = 0; i < 8; i++) {
            float4 v  = hp[i];
            float4 sc = scp[i];
            float4 sh = shp[i];
            v.x = fmaxf(fmaf(v.x, sc.x, sh.x), 0.f);
            v.y = fmaxf(fmaf(v.y, sc.y, sh.y), 0.f);
            v.z = fmaxf(fmaf(v.z, sc.z, sh.z), 0.f);
            v.w = fmaxf(fmaf(v.w, sc.w, sh.w), 0.f);
            u32 h0, l0, h1, l1;
            split2(v.x, v.y, h0, l0);
            split2(v.z, v.w, h1, l1);
            u32 ad = rowb + (((u32)(cb * 2 + i * 8)) ^ xm);
            *reinterpret_cast<u64*>(smc + A_HH + ad) = ((u64)h1 << 32) | h0;
            *reinterpret_cast<u64*>(smc + A_HL + ad) = ((u64)l1 << 32) | l0;
        }
    }
    __syncthreads();

    int obase = (wid & 3) * 32, sbase = (wid >> 2) * 32;
    int m = L >> 3;
    int rA_off = (m & 1) * 8 + (L & 7);
    int kbA_off = (m >> 1) * 16;
    int nrB_off = ((m >> 1) & 1) * 8 + (L & 7);  // B non-trans: n-row offset
    int kbB_off = (m & 1) * 16;

    float dq[2][4][4], dk[2][4][4];
#pragma unroll
    for (int mf = 0; mf < 2; mf++)
#pragma unroll
        for (int nf = 0; nf < 4; nf++)
#pragma unroll
            for (int j = 0; j < 4; j++) { dq[mf][nf][j] = 0.f; dk[mf][nf][j] = 0.f; }

    // phase 1: q and k GEMMs
#pragma unroll
    for (int ks = 0; ks < 8; ks++) {
        u32 bh[4][2], bl[4][2];
#pragma unroll
        for (int np = 0; np < 2; np++) {
            int nrow = sbase + np * 16 + nrB_off;
            u32 ad = (u32)(nrow * 256) + (u32)((ks * 32 + kbB_off) ^ ((nrow & 7) << 4));
            u32 r[4];
            ldsm4(r, sm32 + A_HH + ad);
            bh[np * 2][0] = r[0]; bh[np * 2][1] = r[1];
            bh[np * 2 + 1][0] = r[2]; bh[np * 2 + 1][1] = r[3];
            ldsm4(r, sm32 + A_HL + ad);
            bl[np * 2][0] = r[0]; bl[np * 2][1] = r[1];
            bl[np * 2 + 1][0] = r[2]; bl[np * 2 + 1][1] = r[3];
        }
        u32 ah[2][4], al[2][4];
#pragma unroll
        for (int mf = 0; mf < 2; mf++) {
            int row = obase + mf * 16 + rA_off;
            u32 ad = (u32)(row * 256) + (u32)((ks * 32 + kbA_off) ^ ((row & 7) << 4));
            ldsm4(ah[mf], sm32 + A_QH + ad);
            ldsm4(al[mf], sm32 + A_QL + ad);
        }
#pragma unroll
        for (int mf = 0; mf < 2; mf++)
#pragma unroll
            for (int nf = 0; nf < 4; nf++) {
                mma16816(dq[mf][nf], ah[mf], bh[nf]);
                mma16816(dq[mf][nf], ah[mf], bl[nf]);
                mma16816(dq[mf][nf], al[mf], bh[nf]);
            }
#pragma unroll
        for (int mf = 0; mf < 2; mf++) {
            int row = obase + mf * 16 + rA_off;
            u32 ad = (u32)(row * 256) + (u32)((ks * 32 + kbA_off) ^ ((row & 7) << 4));
            ldsm4(ah[mf], sm32 + A_KH + ad);
            ldsm4(al[mf], sm32 + A_KL + ad);
        }
#pragma unroll
        for (int mf = 0; mf < 2; mf++)
#pragma unroll
            for (int nf = 0; nf < 4; nf++) {
                mma16816(dk[mf][nf], ah[mf], bh[nf]);
                mma16816(dk[mf][nf], ah[mf], bl[nf]);
                mma16816(dk[mf][nf], al[mf], bh[nf]);
            }
    }

    // p = (q+bq)*(k+bk) in-place into dq
    float bqv[2][2], bkv[2][2], bvv[2][2];
#pragma unroll
    for (int mf = 0; mf < 2; mf++)
#pragma unroll
        for (int hf = 0; hf < 2; hf++) {
            int o = obase + mf * 16 + (L >> 2) + hf * 8;
            bqv[mf][hf] = bq[o]; bkv[mf][hf] = bk[o]; bvv[mf][hf] = bv[o];
        }
#pragma unroll
    for (int mf = 0; mf < 2; mf++)
#pragma unroll
        for (int nf = 0; nf < 4; nf++)
#pragma unroll
            for (int j = 0; j < 4; j++) {
                int hf = j >> 1;
                dq[mf][nf][j] = (dq[mf][nf][j] + bqv[mf][hf]) * (dk[mf][nf][j] + bkv[mf][hf]);
            }

    __syncthreads();
    stage_w(smc, A_QH, A_QL, wv, t);   // reuse q-weight buffers for Wv
    __syncthreads();

    // phase 2: v GEMM (dk reused as accumulator)
#pragma unroll
    for (int mf = 0; mf < 2; mf++)
#pragma unroll
        for (int nf = 0; nf < 4; nf++)
#pragma unroll
            for (int j = 0; j < 4; j++) dk[mf][nf][j] = 0.f;

#pragma unroll
    for (int ks = 0; ks < 8; ks++) {
        u32 bh[4][2], bl[4][2];
#pragma unroll
        for (int np = 0; np < 2; np++) {
            int nrow = sbase + np * 16 + nrB_off;
            u32 ad = (u32)(nrow * 256) + (u32)((ks * 32 + kbB_off) ^ ((nrow & 7) << 4));
            u32 r[4];
            ldsm4(r, sm32 + A_HH + ad);
            bh[np * 2][0] = r[0]; bh[np * 2][1] = r[1];
            bh[np * 2 + 1][0] = r[2]; bh[np * 2 + 1][1] = r[3];
            ldsm4(r, sm32 + A_HL + ad);
            bl[np * 2][0] = r[0]; bl[np * 2][1] = r[1];
            bl[np * 2 + 1][0] = r[2]; bl[np * 2 + 1][1] = r[3];
        }
        u32 ah[2][4], al[2][4];
#pragma unroll
        for (int mf = 0; mf < 2; mf++) {
            int row = obase + mf * 16 + rA_off;
            u32 ad = (u32)(row * 256) + (u32)((ks * 32 + kbA_off) ^ ((row & 7) << 4));
            ldsm4(ah[mf], sm32 + A_QH + ad);
            ldsm4(al[mf], sm32 + A_QL + ad);
        }
#pragma unroll
        for (int mf = 0; mf < 2; mf++)
#pragma unroll
            for (int nf = 0; nf < 4; nf++) {
                mma16816(dk[mf][nf], ah[mf], bh[nf]);
                mma16816(dk[mf][nf], ah[mf], bl[nf]);
                mma16816(dk[mf][nf], al[mf], bh[nf]);
            }
    }

    // epilogue: softmax over 16-s groups (quad shfl) + weighted V + residual
    float gm = gamma1[0];
#pragma unroll
    for (int mf = 0; mf < 2; mf++)
#pragma unroll
        for (int hf = 0; hf < 2; hf++)
#pragma unroll
            for (int g = 0; g < 2; g++) {
                float p0 = dq[mf][2 * g][hf * 2],     p1 = dq[mf][2 * g][hf * 2 + 1];
                float p2 = dq[mf][2 * g + 1][hf * 2], p3 = dq[mf][2 * g + 1][hf * 2 + 1];
                float mx = fmaxf(fmaxf(p0, p1), fmaxf(p2, p3));
                mx = fmaxf(mx, __shfl_xor_sync(0xffffffffu, mx, 1));
                mx = fmaxf(mx, __shfl_xor_sync(0xffffffffu, mx, 2));
                float e0 = __expf(p0 - mx), e1 = __expf(p1 - mx);
                float e2 = __expf(p2 - mx), e3 = __expf(p3 - mx);
                float den = e0 + e1 + e2 + e3;
                float bv_ = bvv[mf][hf];
                float acc = e0 * (dk[mf][2 * g][hf * 2] + bv_)
                          + e1 * (dk[mf][2 * g][hf * 2 + 1] + bv_)
                          + e2 * (dk[mf][2 * g + 1][hf * 2] + bv_)
                          + e3 * (dk[mf][2 * g + 1][hf * 2 + 1] + bv_);
                den += __shfl_xor_sync(0xffffffffu, den, 1);
                den += __shfl_xor_sync(0xffffffffu, den, 2);
                acc += __shfl_xor_sync(0xffffffffu, acc, 1);
                acc += __shfl_xor_sync(0xffffffffu, acc, 2);
                if ((L & 3) == 0) {
                    int n = tile * 8 + (wid >> 2) * 2 + g;
                    int o = obase + mf * 16 + (L >> 2) + hf * 8;
                    size_t oi = ((size_t)b * CC + o) * NN + n;
                    out[oi] = x_row[oi] + gm * (acc / den);
                }
            }
}

// ---------------------------------------------------------------------------
extern "C" void kernel_launch(void* const* d_in, const int* in_sizes, int n_in,
                              void* d_out, int out_size) {
    const float* x_row   = (const float*)d_in[0];
    const float* x_local = (const float*)d_in[1];
    const float* w0      = (const float*)d_in[2];
    const float* b0      = (const float*)d_in[3];
    const float* bn_g    = (const float*)d_in[4];
    const float* bn_b    = (const float*)d_in[5];
    const float* wq      = (const float*)d_in[6];
    const float* bq      = (const float*)d_in[7];
    const float* wk      = (const float*)d_in[8];
    const float* bk      = (const float*)d_in[9];
    const float* wv      = (const float*)d_in[10];
    const float* bv      = (const float*)d_in[11];
    const float* gamma1  = (const float*)d_in[12];
    float* out = (float*)d_out;

    cudaFuncSetAttribute(k_conv0, cudaFuncAttributeMaxDynamicSharedMemorySize, C_SMEM);
    cudaFuncSetAttribute(k_attn,  cudaFuncAttributeMaxDynamicSharedMemorySize, A_SMEM);

    k_conv0<<<dim3(TIL, BB), 512, C_SMEM>>>(x_local, w0, b0);
    k_stats<<<1, 1024>>>(bn_g, bn_b);
    k_attn<<<dim3(TIL, BB), 512, A_SMEM>>>(x_row, wq, bq, wk, bk, wv, bv, gamma1, out);
}